// round 9
// baseline (speedup 1.0000x reference)
#include <cuda_runtime.h>

#define NB 16
#define NN 4096
#define ND 64
#define NPOINT 1024
#define NSAMP 32
#define C0 67
#define O0 64
#define O1 64
#define O2 128
#define OUT_XYZ (NB*NPOINT*3)
#define GPB 8

#define RS 34    // Adup row stride in u64 units (even -> ull2-indexable)
#define SG 132   // maxpool scratch stride (floats)

// -------- device scratch (no allocations allowed) --------
__device__ int   g_fps[NB * NPOINT];
__device__ int   g_grp[NB * NPOINT * NSAMP];
__device__ __align__(16) float g_W0t[C0 * O0];   // [c][o]
__device__ __align__(16) float g_W1t[O0 * O1];   // [c][o]
__device__ __align__(16) float g_W2t[O1 * O2];   // [c][o]
__device__ float g_b0f[O0];
__device__ float g_b1f[O1];
__device__ float g_b2f[O2];

// ---- packed f32x2 helpers (each lane: exact fp32 rn ops) ----
#define PACK2(out, lo, hi) \
    asm("mov.b64 %0, {%1, %2};" : "=l"(out) : "f"(lo), "f"(hi))
#define UNPACK2(lo, hi, in) \
    asm("mov.b64 {%0, %1}, %2;" : "=f"(lo), "=f"(hi) : "l"(in))
#define ADD2(out, a, b) \
    asm("add.rn.f32x2 %0, %1, %2;" : "=l"(out) : "l"(a), "l"(b))
#define MUL2(out, a, b) \
    asm("mul.rn.f32x2 %0, %1, %2;" : "=l"(out) : "l"(a), "l"(b))
#define FMA2(out, a, b, c) \
    asm("fma.rn.f32x2 %0, %1, %2, %3;" : "=l"(out) : "l"(a), "l"(b), "l"(c))
#define FMA2A(acc, a, b) \
    asm("fma.rn.f32x2 %0, %1, %2, %0;" : "+l"(acc) : "l"(a), "l"(b))

// ===================== BN fold (writes transposed weights) =====================
__global__ void fold_kernel(
    const float* __restrict__ W0, const float* __restrict__ b0, const float* __restrict__ g0,
    const float* __restrict__ be0, const float* __restrict__ m0, const float* __restrict__ v0,
    const float* __restrict__ W1, const float* __restrict__ b1, const float* __restrict__ g1,
    const float* __restrict__ be1, const float* __restrict__ m1, const float* __restrict__ v1,
    const float* __restrict__ W2, const float* __restrict__ b2, const float* __restrict__ g2,
    const float* __restrict__ be2, const float* __restrict__ m2, const float* __restrict__ v2)
{
    int t = threadIdx.x;
    int nt = blockDim.x;
    for (int e = t; e < C0 * O0; e += nt) {
        int c = e >> 6, o = e & 63;
        g_W0t[e] = W0[o * C0 + c] * (g0[o] * rsqrtf(v0[o] + 1e-5f));
    }
    for (int e = t; e < O0 * O1; e += nt) {
        int c = e >> 6, o = e & 63;
        g_W1t[e] = W1[o * O0 + c] * (g1[o] * rsqrtf(v1[o] + 1e-5f));
    }
    for (int e = t; e < O1 * O2; e += nt) {
        int c = e >> 7, o = e & 127;
        g_W2t[e] = W2[o * O1 + c] * (g2[o] * rsqrtf(v2[o] + 1e-5f));
    }
    for (int o = t; o < O0; o += nt)
        g_b0f[o] = (b0[o] - m0[o]) * (g0[o] * rsqrtf(v0[o] + 1e-5f)) + be0[o];
    for (int o = t; o < O1; o += nt)
        g_b1f[o] = (b1[o] - m1[o]) * (g1[o] * rsqrtf(v1[o] + 1e-5f)) + be1[o];
    for (int o = t; o < O2; o += nt)
        g_b2f[o] = (b2[o] - m2[o]) * (g2[o] * rsqrtf(v2[o] + 1e-5f)) + be2[o];
}

// ===================== FPS =====================
// Warp argmax via REDUX intrinsics; cross-warp via parity-double-buffered smem
// keys + ONE barrier/iter + redundant per-warp bfly reduce. No atomics.
__global__ __launch_bounds__(512) void fps_kernel(const float* __restrict__ xyz)
{
    __shared__ unsigned long long swk[2][16];

    int b = blockIdx.x;
    int t = threadIdx.x;
    int w = t >> 5;
    int lane = t & 31;
    const float* p = xyz + (size_t)b * NN * 3;

    float dl[8];
    unsigned long long px2[4], py2[4], pz2[4];
#pragma unroll
    for (int j = 0; j < 4; j++) {
        int p0 = t + (2 * j) * 512;
        int p1 = t + (2 * j + 1) * 512;
        float x0 = p[3 * p0], y0 = p[3 * p0 + 1], z0 = p[3 * p0 + 2];
        float x1 = p[3 * p1], y1 = p[3 * p1 + 1], z1 = p[3 * p1 + 2];
        PACK2(px2[j], x0, x1);
        PACK2(py2[j], y0, y1);
        PACK2(pz2[j], z0, z1);
        dl[2 * j] = 1e10f;
        dl[2 * j + 1] = 1e10f;
    }
    if (t == 0) g_fps[b * NPOINT] = 0;

    float cx = p[0], cy = p[1], cz = p[2];
    for (int it = 1; it < NPOINT; it++) {
        unsigned long long ncx2, ncy2, ncz2;
        {
            float nx = -cx, ny = -cy, nz = -cz;
            PACK2(ncx2, nx, nx);
            PACK2(ncy2, ny, ny);
            PACK2(ncz2, nz, nz);
        }
        float bv = -1.0f;
        int bi = 0;
#pragma unroll
        for (int j = 0; j < 4; j++) {
            unsigned long long dxp, dyp, dzp, dp;
            ADD2(dxp, px2[j], ncx2);          // x - cx  (== x + (-cx), exact)
            ADD2(dyp, py2[j], ncy2);
            ADD2(dzp, pz2[j], ncz2);
            MUL2(dp, dxp, dxp);
            FMA2(dp, dyp, dyp, dp);
            FMA2(dp, dzp, dzp, dp);
            float d0, d1;
            UNPACK2(d0, d1, dp);
            float dn0 = fminf(dl[2 * j], d0);
            dl[2 * j] = dn0;
            if (dn0 > bv) { bv = dn0; bi = t + (2 * j) * 512; }
            float dn1 = fminf(dl[2 * j + 1], d1);
            dl[2 * j + 1] = dn1;
            if (dn1 > bv) { bv = dn1; bi = t + (2 * j + 1) * 512; }
        }
        // warp argmax: REDUX max on value bits (nonneg float -> monotonic u32),
        // then REDUX min over candidate indices for exact first-index ties.
        unsigned vb = __float_as_uint(bv);
        unsigned wmax = __reduce_max_sync(0xffffffffu, vb);
        unsigned cand = (vb == wmax) ? (unsigned)bi : 0xffffffffu;
        unsigned widx = __reduce_min_sync(0xffffffffu, cand);
        int par = it & 1;
        if (lane == 0)
            swk[par][w] = ((unsigned long long)wmax << 12) |
                          (unsigned)(4095 - widx);
        __syncthreads();
        // every warp redundantly reduces the 16 keys (no 2nd barrier; parity
        // buffer prevents next-iter overwrite races)
        unsigned long long k = swk[par][lane & 15];
#pragma unroll
        for (int off = 8; off > 0; off >>= 1) {
            unsigned long long ok = __shfl_xor_sync(0xffffffffu, k, off);
            if (ok > k) k = ok;
        }
        int idx = 4095 - (int)(k & 0xFFFu);
        cx = p[3 * idx]; cy = p[3 * idx + 1]; cz = p[3 * idx + 2];  // uniform L1-hit
        if (t == 0) g_fps[b * NPOINT + it] = idx;
    }
}

// ===================== ball query (+new_xyz write) =====================
__global__ __launch_bounds__(256) void ballquery_kernel(const float* __restrict__ xyz,
                                                        float* __restrict__ out)
{
    int gw = (blockIdx.x * 256 + threadIdx.x) >> 5;
    int lane = threadIdx.x & 31;
    if (gw >= NB * NPOINT) return;
    int b = gw >> 10;
    const float* p = xyz + (size_t)b * NN * 3;

    int ci = g_fps[gw];
    float cx = p[3 * ci + 0];
    float cy = p[3 * ci + 1];
    float cz = p[3 * ci + 2];
    if (lane < 3) out[(size_t)gw * 3 + lane] = p[3 * ci + lane];

    float sn = fmaf(cz, cz, fmaf(cy, cy, __fmul_rn(cx, cx)));
    int* grp = g_grp + (size_t)gw * NSAMP;

    int cnt = 0;
    int first = ci;
    bool gotfirst = false;
    for (int base = 0; base < NN && cnt < NSAMP; base += 32) {
        int i = base + lane;
        float x = p[3 * i + 0], y = p[3 * i + 1], z = p[3 * i + 2];
        float sp = fmaf(z, z, fmaf(y, y, __fmul_rn(x, x)));
        float dt = fmaf(cz, z, fmaf(cy, y, __fmul_rn(cx, x)));
        float d2 = fmaf(-2.0f, dt, sn + sp);
        bool isin = !(d2 > 0.04f);
        unsigned m = __ballot_sync(0xffffffffu, isin);
        if (!gotfirst && m) { first = base + __ffs(m) - 1; gotfirst = true; }
        int pos = cnt + __popc(m & ((1u << lane) - 1u));
        if (isin && pos < NSAMP) grp[pos] = i;
        cnt += __popc(m);
    }
    if (cnt < NSAMP) {
        int p0 = cnt + lane;
        if (p0 < NSAMP) grp[p0] = first;
    }
}

// ===================== fused gather + MLP(3) + maxpool =====================
// FFMA2 (fma.rn.f32x2) mainloops: activations stored PRE-DUPLICATED (a,a) as u64
// so k-side pairs need no packing; weights [c][o] so j-pairs (w_j0,w_j1) come
// straight from ulonglong2 loads. Bit-identical fp32 rn arithmetic.
__global__ __launch_bounds__(128, 6) void mlp_kernel(const float* __restrict__ xyz,
                                                     const float* __restrict__ pts,
                                                     float* __restrict__ out)
{
    __shared__ __align__(16) unsigned long long Adup[C0 * RS];  // 2278 u64 = 18.2KB
    __shared__ __align__(16) float sW0[C0 * O0];                // 17.2KB
    __shared__ float sb[256];                                   // b0|b1|b2
    __shared__ int   sidx[NSAMP];
    __shared__ float scen[3];

    int t = threadIdx.x;
    int kt = t >> 4;   // k base = kt*4 (0..28)
    int ot = t & 15;   // o base = ot*4 (L0/L1) or ot*8 (L2)

    {   // contiguous float4 copy of transposed W0
        const float4* src = reinterpret_cast<const float4*>(g_W0t);
        float4* dst = reinterpret_cast<float4*>(sW0);
        for (int e = t; e < C0 * O0 / 4; e += 128) dst[e] = src[e];
    }
    if (t < 64) sb[t] = g_b0f[t];
    else        sb[t] = g_b1f[t - 64];
    for (int e = t; e < O2; e += 128) sb[128 + e] = g_b2f[e];
    __syncthreads();

    const ulonglong2* Ad = reinterpret_cast<const ulonglong2*>(Adup);  // row stride 17

    for (int g = 0; g < GPB; g++) {
        int gw = blockIdx.x * GPB + g;
        int b = gw >> 10;
        const float* pxyz = xyz + (size_t)b * NN * 3;
        const float* ppts = pts + (size_t)b * NN * ND;

        if (t < NSAMP) sidx[t] = g_grp[(size_t)gw * NSAMP + t];
        if (t < 3)     scen[t] = out[(size_t)gw * 3 + t];
        __syncthreads();

        // gather (coalesced reads), duplicated write Adup[c][k] = (v,v)
        for (int e = t; e < NSAMP * C0; e += 128) {
            int k = e / C0;
            int c = e - k * C0;
            int id = sidx[k];
            float v;
            if (c < 3) v = pxyz[3 * id + c] - scen[c];
            else       v = ppts[(size_t)id * ND + (c - 3)];
            unsigned long long vv;
            PACK2(vv, v, v);
            Adup[c * RS + k] = vv;
        }
        __syncthreads();

        // ---- Layer 0: k in {kt*4+i}, o in {ot*4+j} ----
        {
            unsigned long long acc[4][2] = {};   // [i][jp]; 0 bits == (+0,+0)
            for (int c = 0; c < C0; c++) {
                ulonglong2 a01 = Ad[c * 17 + kt * 2];       // (a0,a0),(a1,a1)
                ulonglong2 a23 = Ad[c * 17 + kt * 2 + 1];   // (a2,a2),(a3,a3)
                ulonglong2 wp  = *reinterpret_cast<const ulonglong2*>(
                                     &sW0[c * O0 + ot * 4]); // (w0,w1),(w2,w3)
                FMA2A(acc[0][0], a01.x, wp.x); FMA2A(acc[0][1], a01.x, wp.y);
                FMA2A(acc[1][0], a01.y, wp.x); FMA2A(acc[1][1], a01.y, wp.y);
                FMA2A(acc[2][0], a23.x, wp.x); FMA2A(acc[2][1], a23.x, wp.y);
                FMA2A(acc[3][0], a23.y, wp.x); FMA2A(acc[3][1], a23.y, wp.y);
            }
            __syncthreads();   // all Adup reads done
#pragma unroll
            for (int i = 0; i < 4; i++)
#pragma unroll
                for (int jp = 0; jp < 2; jp++) {
                    float s0, s1;
                    UNPACK2(s0, s1, acc[i][jp]);
                    int o0 = ot * 4 + jp * 2;
                    float r0 = fmaxf(s0 + sb[o0], 0.0f);
                    float r1 = fmaxf(s1 + sb[o0 + 1], 0.0f);
                    unsigned long long v0, v1;
                    PACK2(v0, r0, r0);
                    PACK2(v1, r1, r1);
                    Adup[o0 * RS + kt * 4 + i] = v0;
                    Adup[(o0 + 1) * RS + kt * 4 + i] = v1;
                }
        }
        __syncthreads();

        // ---- Layer 1: W1 from global (L1-resident ulonglong2) ----
        {
            unsigned long long acc[4][2] = {};
            const ulonglong2* w1v = reinterpret_cast<const ulonglong2*>(g_W1t); // row=16
            for (int c = 0; c < O0; c++) {
                ulonglong2 a01 = Ad[c * 17 + kt * 2];
                ulonglong2 a23 = Ad[c * 17 + kt * 2 + 1];
                ulonglong2 wp  = __ldg(&w1v[c * 16 + ot]);
                FMA2A(acc[0][0], a01.x, wp.x); FMA2A(acc[0][1], a01.x, wp.y);
                FMA2A(acc[1][0], a01.y, wp.x); FMA2A(acc[1][1], a01.y, wp.y);
                FMA2A(acc[2][0], a23.x, wp.x); FMA2A(acc[2][1], a23.x, wp.y);
                FMA2A(acc[3][0], a23.y, wp.x); FMA2A(acc[3][1], a23.y, wp.y);
            }
            __syncthreads();
#pragma unroll
            for (int i = 0; i < 4; i++)
#pragma unroll
                for (int jp = 0; jp < 2; jp++) {
                    float s0, s1;
                    UNPACK2(s0, s1, acc[i][jp]);
                    int o0 = ot * 4 + jp * 2;
                    float r0 = fmaxf(s0 + sb[64 + o0], 0.0f);
                    float r1 = fmaxf(s1 + sb[64 + o0 + 1], 0.0f);
                    unsigned long long v0, v1;
                    PACK2(v0, r0, r0);
                    PACK2(v1, r1, r1);
                    Adup[o0 * RS + kt * 4 + i] = v0;
                    Adup[(o0 + 1) * RS + kt * 4 + i] = v1;
                }
        }
        __syncthreads();

        // ---- Layer 2: o in {ot*8+j}; W2 global ulonglong2; then max over k ----
        {
            unsigned long long acc[4][4] = {};   // [i][jp]
            const ulonglong2* w2v = reinterpret_cast<const ulonglong2*>(g_W2t); // row=32
            for (int c = 0; c < O1; c++) {
                ulonglong2 a01 = Ad[c * 17 + kt * 2];
                ulonglong2 a23 = Ad[c * 17 + kt * 2 + 1];
                ulonglong2 wA  = __ldg(&w2v[c * 32 + ot * 2]);      // (w0,w1),(w2,w3)
                ulonglong2 wB  = __ldg(&w2v[c * 32 + ot * 2 + 1]);  // (w4,w5),(w6,w7)
                FMA2A(acc[0][0], a01.x, wA.x); FMA2A(acc[0][1], a01.x, wA.y);
                FMA2A(acc[0][2], a01.x, wB.x); FMA2A(acc[0][3], a01.x, wB.y);
                FMA2A(acc[1][0], a01.y, wA.x); FMA2A(acc[1][1], a01.y, wA.y);
                FMA2A(acc[1][2], a01.y, wB.x); FMA2A(acc[1][3], a01.y, wB.y);
                FMA2A(acc[2][0], a23.x, wA.x); FMA2A(acc[2][1], a23.x, wA.y);
                FMA2A(acc[2][2], a23.x, wB.x); FMA2A(acc[2][3], a23.x, wB.y);
                FMA2A(acc[3][0], a23.y, wA.x); FMA2A(acc[3][1], a23.y, wA.y);
                FMA2A(acc[3][2], a23.y, wB.x); FMA2A(acc[3][3], a23.y, wB.y);
            }
            __syncthreads();     // Adup reads done; reuse as float gmax[8][SG]
            float* gmax = reinterpret_cast<float*>(Adup);
#pragma unroll
            for (int jp = 0; jp < 4; jp++) {
                float s0[4], s1[4];
#pragma unroll
                for (int i = 0; i < 4; i++) UNPACK2(s0[i], s1[i], acc[i][jp]);
                int o0 = ot * 8 + jp * 2;
                float bias0 = sb[128 + o0];
                float bias1 = sb[128 + o0 + 1];
                float pm0 = fmaxf(s0[0] + bias0, 0.0f);
                float pm1 = fmaxf(s1[0] + bias1, 0.0f);
#pragma unroll
                for (int i = 1; i < 4; i++) {
                    pm0 = fmaxf(pm0, fmaxf(s0[i] + bias0, 0.0f));
                    pm1 = fmaxf(pm1, fmaxf(s1[i] + bias1, 0.0f));
                }
                gmax[kt * SG + o0] = pm0;
                gmax[kt * SG + o0 + 1] = pm1;
            }
            __syncthreads();
            float mx = gmax[t];
#pragma unroll
            for (int q = 1; q < 8; q++) mx = fmaxf(mx, gmax[q * SG + t]);
            out[OUT_XYZ + (size_t)gw * O2 + t] = mx;
        }
        __syncthreads();   // protect Adup/sidx before next group's writes
    }
}

// ===================== launch =====================
extern "C" void kernel_launch(void* const* d_in, const int* in_sizes, int n_in,
                              void* d_out, int out_size)
{
    const float* xyz = (const float*)d_in[0];
    const float* pts = (const float*)d_in[1];
    const float* W0  = (const float*)d_in[2];
    const float* b0  = (const float*)d_in[3];
    const float* g0  = (const float*)d_in[4];
    const float* be0 = (const float*)d_in[5];
    const float* m0  = (const float*)d_in[6];
    const float* v0  = (const float*)d_in[7];
    const float* W1  = (const float*)d_in[8];
    const float* b1  = (const float*)d_in[9];
    const float* g1  = (const float*)d_in[10];
    const float* be1 = (const float*)d_in[11];
    const float* m1  = (const float*)d_in[12];
    const float* v1  = (const float*)d_in[13];
    const float* W2  = (const float*)d_in[14];
    const float* b2  = (const float*)d_in[15];
    const float* g2  = (const float*)d_in[16];
    const float* be2 = (const float*)d_in[17];
    const float* m2  = (const float*)d_in[18];
    const float* v2  = (const float*)d_in[19];
    float* out = (float*)d_out;

    // Kernel launches ONLY — graph-capturable. No dynamic smem, no attribute calls.
    fold_kernel<<<1, 256>>>(W0, b0, g0, be0, m0, v0,
                            W1, b1, g1, be1, m1, v1,
                            W2, b2, g2, be2, m2, v2);
    fps_kernel<<<NB, 512>>>(xyz);
    ballquery_kernel<<<(NB * NPOINT) / 8, 256>>>(xyz, out);
    mlp_kernel<<<(NB * NPOINT) / GPB, 128>>>(xyz, pts, out);
}

// round 10
// speedup vs baseline: 1.7390x; 1.7390x over previous
#include <cuda_runtime.h>

#define NB 16
#define NN 4096
#define ND 64
#define NPOINT 1024
#define NSAMP 32
#define C0 67
#define O0 64
#define O1 64
#define O2 128
#define OUT_XYZ (NB*NPOINT*3)
#define GPB 8

// smem strides (mlp)
#define S0 67   // W0 row stride
#define S1 65   // W1 row stride (odd -> conflict-free)
#define SH 68   // activation row stride
#define SG 132  // maxpool scratch stride

// -------- device scratch (no allocations allowed) --------
__device__ int   g_fps[NB * NPOINT];
__device__ int   g_grp[NB * NPOINT * NSAMP];
__device__ float g_W0f[O0 * C0];                 // [o][c]
__device__ float g_b0f[O0];
__device__ float g_W1f[O1 * O0];                 // [o][c]
__device__ float g_b1f[O1];
__device__ __align__(16) float g_W2t[O1 * O2];   // transposed [c][o]
__device__ float g_b2f[O2];

// ---- packed f32x2 helpers (each lane: exact fp32 rn ops) ----
#define PACK2(out, lo, hi) \
    asm("mov.b64 %0, {%1, %2};" : "=l"(out) : "f"(lo), "f"(hi))
#define UNPACK2(lo, hi, in) \
    asm("mov.b64 {%0, %1}, %2;" : "=f"(lo), "=f"(hi) : "l"(in))
#define ADD2(out, a, b) \
    asm("add.rn.f32x2 %0, %1, %2;" : "=l"(out) : "l"(a), "l"(b))
#define MUL2(out, a, b) \
    asm("mul.rn.f32x2 %0, %1, %2;" : "=l"(out) : "l"(a), "l"(b))
#define FMA2(out, a, b, c) \
    asm("fma.rn.f32x2 %0, %1, %2, %3;" : "=l"(out) : "l"(a), "l"(b), "l"(c))

// ===================== BN fold =====================
__global__ void fold_kernel(
    const float* __restrict__ W0, const float* __restrict__ b0, const float* __restrict__ g0,
    const float* __restrict__ be0, const float* __restrict__ m0, const float* __restrict__ v0,
    const float* __restrict__ W1, const float* __restrict__ b1, const float* __restrict__ g1,
    const float* __restrict__ be1, const float* __restrict__ m1, const float* __restrict__ v1,
    const float* __restrict__ W2, const float* __restrict__ b2, const float* __restrict__ g2,
    const float* __restrict__ be2, const float* __restrict__ m2, const float* __restrict__ v2)
{
    int t = threadIdx.x;
    int nt = blockDim.x;
    for (int e = t; e < O0 * C0; e += nt) {
        int o = e / C0;
        g_W0f[e] = W0[e] * (g0[o] * rsqrtf(v0[o] + 1e-5f));
    }
    for (int e = t; e < O1 * O0; e += nt) {
        int o = e >> 6;
        g_W1f[e] = W1[e] * (g1[o] * rsqrtf(v1[o] + 1e-5f));
    }
    // W2 transposed: g_W2t[c*128 + o] = W2[o*64 + c] * scale(o)
    for (int e = t; e < O2 * O1; e += nt) {
        int c = e >> 7;          // 0..63
        int o = e & 127;         // 0..127
        g_W2t[e] = W2[o * O1 + c] * (g2[o] * rsqrtf(v2[o] + 1e-5f));
    }
    for (int o = t; o < O0; o += nt)
        g_b0f[o] = (b0[o] - m0[o]) * (g0[o] * rsqrtf(v0[o] + 1e-5f)) + be0[o];
    for (int o = t; o < O1; o += nt)
        g_b1f[o] = (b1[o] - m1[o]) * (g1[o] * rsqrtf(v1[o] + 1e-5f)) + be1[o];
    for (int o = t; o < O2; o += nt)
        g_b2f[o] = (b2[o] - m2[o]) * (g2[o] * rsqrtf(v2[o] + 1e-5f)) + be2[o];
}

// ===================== FPS =====================
// Warp argmax via REDUX intrinsics; cross-warp via parity-double-buffered smem
// keys + ONE barrier/iter + redundant per-warp bfly reduce. No atomics.
__global__ __launch_bounds__(512) void fps_kernel(const float* __restrict__ xyz)
{
    __shared__ unsigned long long swk[2][16];

    int b = blockIdx.x;
    int t = threadIdx.x;
    int w = t >> 5;
    int lane = t & 31;
    const float* p = xyz + (size_t)b * NN * 3;

    float dl[8];
    unsigned long long px2[4], py2[4], pz2[4];
#pragma unroll
    for (int j = 0; j < 4; j++) {
        int p0 = t + (2 * j) * 512;
        int p1 = t + (2 * j + 1) * 512;
        float x0 = p[3 * p0], y0 = p[3 * p0 + 1], z0 = p[3 * p0 + 2];
        float x1 = p[3 * p1], y1 = p[3 * p1 + 1], z1 = p[3 * p1 + 2];
        PACK2(px2[j], x0, x1);
        PACK2(py2[j], y0, y1);
        PACK2(pz2[j], z0, z1);
        dl[2 * j] = 1e10f;
        dl[2 * j + 1] = 1e10f;
    }
    if (t == 0) g_fps[b * NPOINT] = 0;

    float cx = p[0], cy = p[1], cz = p[2];
    for (int it = 1; it < NPOINT; it++) {
        unsigned long long ncx2, ncy2, ncz2;
        {
            float nx = -cx, ny = -cy, nz = -cz;
            PACK2(ncx2, nx, nx);
            PACK2(ncy2, ny, ny);
            PACK2(ncz2, nz, nz);
        }
        float bv = -1.0f;
        int bi = 0;
#pragma unroll
        for (int j = 0; j < 4; j++) {
            unsigned long long dxp, dyp, dzp, dp;
            ADD2(dxp, px2[j], ncx2);          // x - cx  (== x + (-cx), exact)
            ADD2(dyp, py2[j], ncy2);
            ADD2(dzp, pz2[j], ncz2);
            MUL2(dp, dxp, dxp);
            FMA2(dp, dyp, dyp, dp);
            FMA2(dp, dzp, dzp, dp);
            float d0, d1;
            UNPACK2(d0, d1, dp);
            float dn0 = fminf(dl[2 * j], d0);
            dl[2 * j] = dn0;
            if (dn0 > bv) { bv = dn0; bi = t + (2 * j) * 512; }
            float dn1 = fminf(dl[2 * j + 1], d1);
            dl[2 * j + 1] = dn1;
            if (dn1 > bv) { bv = dn1; bi = t + (2 * j + 1) * 512; }
        }
        // warp argmax: REDUX max on value bits (nonneg float -> monotonic u32),
        // then REDUX min over candidate indices for exact first-index ties.
        unsigned vb = __float_as_uint(bv);
        unsigned wmax = __reduce_max_sync(0xffffffffu, vb);
        unsigned cand = (vb == wmax) ? (unsigned)bi : 0xffffffffu;
        unsigned widx = __reduce_min_sync(0xffffffffu, cand);
        int par = it & 1;
        if (lane == 0)
            swk[par][w] = ((unsigned long long)wmax << 12) |
                          (unsigned)(4095 - widx);
        __syncthreads();
        // every warp redundantly reduces the 16 keys (no 2nd barrier; parity
        // buffer prevents next-iter overwrite races)
        unsigned long long k = swk[par][lane & 15];
#pragma unroll
        for (int off = 8; off > 0; off >>= 1) {
            unsigned long long ok = __shfl_xor_sync(0xffffffffu, k, off);
            if (ok > k) k = ok;
        }
        int idx = 4095 - (int)(k & 0xFFFu);
        cx = p[3 * idx]; cy = p[3 * idx + 1]; cz = p[3 * idx + 2];  // uniform L1-hit
        if (t == 0) g_fps[b * NPOINT + it] = idx;
    }
}

// ===================== ball query (+new_xyz write) =====================
__global__ __launch_bounds__(256) void ballquery_kernel(const float* __restrict__ xyz,
                                                        float* __restrict__ out)
{
    int gw = (blockIdx.x * 256 + threadIdx.x) >> 5;
    int lane = threadIdx.x & 31;
    if (gw >= NB * NPOINT) return;
    int b = gw >> 10;
    const float* p = xyz + (size_t)b * NN * 3;

    int ci = g_fps[gw];
    float cx = p[3 * ci + 0];
    float cy = p[3 * ci + 1];
    float cz = p[3 * ci + 2];
    if (lane < 3) out[(size_t)gw * 3 + lane] = p[3 * ci + lane];

    float sn = fmaf(cz, cz, fmaf(cy, cy, __fmul_rn(cx, cx)));
    int* grp = g_grp + (size_t)gw * NSAMP;

    int cnt = 0;
    int first = ci;
    bool gotfirst = false;
    for (int base = 0; base < NN && cnt < NSAMP; base += 32) {
        int i = base + lane;
        float x = p[3 * i + 0], y = p[3 * i + 1], z = p[3 * i + 2];
        float sp = fmaf(z, z, fmaf(y, y, __fmul_rn(x, x)));
        float dt = fmaf(cz, z, fmaf(cy, y, __fmul_rn(cx, x)));
        float d2 = fmaf(-2.0f, dt, sn + sp);
        bool isin = !(d2 > 0.04f);
        unsigned m = __ballot_sync(0xffffffffu, isin);
        if (!gotfirst && m) { first = base + __ffs(m) - 1; gotfirst = true; }
        int pos = cnt + __popc(m & ((1u << lane) - 1u));
        if (isin && pos < NSAMP) grp[pos] = i;
        cnt += __popc(m);
    }
    if (cnt < NSAMP) {
        int p0 = cnt + lane;
        if (p0 < NSAMP) grp[p0] = first;
    }
}

// ===================== fused gather + MLP(3) + maxpool =====================
// R5 version verbatim (measured 595.6 us — best MLP so far).
__global__ __launch_bounds__(128) void mlp_kernel(const float* __restrict__ xyz,
                                                  const float* __restrict__ pts,
                                                  float* __restrict__ out)
{
    __shared__ float sW0[O0 * S0];     // 4288 floats
    __shared__ float sW1[O1 * S1];     // 4160
    __shared__ float sb[256 + O2];     // [0,64)=b0 [64,128)=b1 [128,256)=b2
    __shared__ float hin[NSAMP * SH];  // 2176 ; reused as gmax[8][SG]
    __shared__ int   sidx[NSAMP];
    __shared__ float scen[3];

    int t = threadIdx.x;
    int kt = t >> 4;   // 0..7  (k = kt + 8*i)
    int ot = t & 15;   // 0..15

    for (int e = t; e < O0 * C0; e += 128) sW0[e] = g_W0f[e];
    for (int e = t; e < O1 * O0; e += 128) sW1[(e >> 6) * S1 + (e & 63)] = g_W1f[e];
    if (t < 64)       sb[t] = g_b0f[t];
    else              sb[t] = g_b1f[t - 64];
    for (int e = t; e < O2; e += 128) sb[128 + e] = g_b2f[e];
    __syncthreads();

    for (int g = 0; g < GPB; g++) {
        int gw = blockIdx.x * GPB + g;
        int b = gw >> 10;
        const float* pxyz = xyz + (size_t)b * NN * 3;
        const float* ppts = pts + (size_t)b * NN * ND;

        if (t < NSAMP) sidx[t] = g_grp[(size_t)gw * NSAMP + t];
        if (t < 3)     scen[t] = out[(size_t)gw * 3 + t];
        __syncthreads();

        // gather: hin[k][c] = c<3 ? xyz[id][c]-cen[c] : points[id][c-3]
        for (int e = t; e < NSAMP * C0; e += 128) {
            int k = e / C0;
            int c = e - k * C0;
            int id = sidx[k];
            float v;
            if (c < 3) v = pxyz[3 * id + c] - scen[c];
            else       v = ppts[(size_t)id * ND + (c - 3)];
            hin[k * SH + c] = v;
        }
        __syncthreads();

        // ---- Layer 0: [32,67] x W0[64,67]^T ; regs -> writeback into hin ----
        {
            float acc[4][4] = {};
            for (int c = 0; c < C0; c++) {
                float a[4], w[4];
#pragma unroll
                for (int i = 0; i < 4; i++) a[i] = hin[(kt + 8 * i) * SH + c];
#pragma unroll
                for (int j = 0; j < 4; j++) w[j] = sW0[(ot + 16 * j) * S0 + c];
#pragma unroll
                for (int i = 0; i < 4; i++)
#pragma unroll
                    for (int j = 0; j < 4; j++) acc[i][j] = fmaf(a[i], w[j], acc[i][j]);
            }
            __syncthreads();   // all reads of hin done
#pragma unroll
            for (int i = 0; i < 4; i++)
#pragma unroll
                for (int j = 0; j < 4; j++) {
                    int k = kt + 8 * i, o = ot + 16 * j;
                    hin[k * SH + o] = fmaxf(acc[i][j] + sb[o], 0.0f);
                }
        }
        __syncthreads();

        // ---- Layer 1: [32,64] x W1[64,64]^T ; regs -> writeback into hin ----
        {
            float acc[4][4] = {};
            for (int c = 0; c < O0; c++) {
                float a[4], w[4];
#pragma unroll
                for (int i = 0; i < 4; i++) a[i] = hin[(kt + 8 * i) * SH + c];
#pragma unroll
                for (int j = 0; j < 4; j++) w[j] = sW1[(ot + 16 * j) * S1 + c];
#pragma unroll
                for (int i = 0; i < 4; i++)
#pragma unroll
                    for (int j = 0; j < 4; j++) acc[i][j] = fmaf(a[i], w[j], acc[i][j]);
            }
            __syncthreads();
#pragma unroll
            for (int i = 0; i < 4; i++)
#pragma unroll
                for (int j = 0; j < 4; j++) {
                    int k = kt + 8 * i, o = ot + 16 * j;
                    hin[k * SH + o] = fmaxf(acc[i][j] + sb[64 + o], 0.0f);
                }
        }
        __syncthreads();

        // ---- Layer 2: [32,64] x W2t (global, transposed, float4, L1-resident),
        //      then max over k ----
        {
            float acc[4][8] = {};
            const float4* W2v = reinterpret_cast<const float4*>(g_W2t);
            for (int c = 0; c < O1; c++) {
                float a[4];
#pragma unroll
                for (int i = 0; i < 4; i++) a[i] = hin[(kt + 8 * i) * SH + c];
                // o = ot*8 + j  (j = 0..7); two contiguous float4 loads
                float4 w0 = __ldg(&W2v[c * 32 + ot * 2 + 0]);
                float4 w1 = __ldg(&W2v[c * 32 + ot * 2 + 1]);
                float w[8] = {w0.x, w0.y, w0.z, w0.w, w1.x, w1.y, w1.z, w1.w};
#pragma unroll
                for (int i = 0; i < 4; i++)
#pragma unroll
                    for (int j = 0; j < 8; j++) acc[i][j] = fmaf(a[i], w[j], acc[i][j]);
            }
            __syncthreads();   // hin reads done; reuse as gmax[8][SG]
            float* gmax = hin;
#pragma unroll
            for (int j = 0; j < 8; j++) {
                int o = ot * 8 + j;
                float bias = sb[128 + o];
                float pm = fmaxf(acc[0][j] + bias, 0.0f);
#pragma unroll
                for (int i = 1; i < 4; i++)
                    pm = fmaxf(pm, fmaxf(acc[i][j] + bias, 0.0f));
                gmax[kt * SG + o] = pm;
            }
            __syncthreads();
            // final max over 8 kt slices; thread t handles channel o = t
            float mx = gmax[t];
#pragma unroll
            for (int q = 1; q < 8; q++) mx = fmaxf(mx, gmax[q * SG + t]);
            out[OUT_XYZ + (size_t)gw * O2 + t] = mx;
        }
        __syncthreads();   // protect hin/sidx before next group's writes
    }
}

// ===================== launch =====================
extern "C" void kernel_launch(void* const* d_in, const int* in_sizes, int n_in,
                              void* d_out, int out_size)
{
    const float* xyz = (const float*)d_in[0];
    const float* pts = (const float*)d_in[1];
    const float* W0  = (const float*)d_in[2];
    const float* b0  = (const float*)d_in[3];
    const float* g0  = (const float*)d_in[4];
    const float* be0 = (const float*)d_in[5];
    const float* m0  = (const float*)d_in[6];
    const float* v0  = (const float*)d_in[7];
    const float* W1  = (const float*)d_in[8];
    const float* b1  = (const float*)d_in[9];
    const float* g1  = (const float*)d_in[10];
    const float* be1 = (const float*)d_in[11];
    const float* m1  = (const float*)d_in[12];
    const float* v1  = (const float*)d_in[13];
    const float* W2  = (const float*)d_in[14];
    const float* b2  = (const float*)d_in[15];
    const float* g2  = (const float*)d_in[16];
    const float* be2 = (const float*)d_in[17];
    const float* m2  = (const float*)d_in[18];
    const float* v2  = (const float*)d_in[19];
    float* out = (float*)d_out;

    // Kernel launches ONLY — graph-capturable. No dynamic smem, no attribute calls.
    fold_kernel<<<1, 256>>>(W0, b0, g0, be0, m0, v0,
                            W1, b1, g1, be1, m1, v1,
                            W2, b2, g2, be2, m2, v2);
    fps_kernel<<<NB, 512>>>(xyz);
    ballquery_kernel<<<(NB * NPOINT) / 8, 256>>>(xyz, out);
    mlp_kernel<<<(NB * NPOINT) / GPB, 128>>>(xyz, pts, out);
}